// round 3
// baseline (speedup 1.0000x reference)
#include <cuda_runtime.h>
#include <cstdint>

// Problem constants (fixed by setup_inputs)
#define B_      16
#define T_      1024
#define D_      384
#define MAXDUR_ 4
#define OUTLEN_ (T_ * MAXDUR_)      // 4096
#define D4_     (D_ / 4)            // 96 float4 per row

#define G_THREADS    384            // gather CTA size
#define ROWS_PER_CTA 32             // 32 rows * 96 f4 = 3072 = 384 * 8
#define RPT          8              // rows per thread

// Scratch: per-output-frame source index, -1 => pad (zero fill)
__device__ int g_idx[B_ * OUTLEN_];

// ---------------------------------------------------------------------------
// Kernel 1: warp-shuffle inclusive scan of durations + scatter-expand of the
// index table. 16 blocks (one per batch row), 1024 threads.
// ---------------------------------------------------------------------------
__global__ void __launch_bounds__(T_) scan_idx_kernel(const int* __restrict__ ds) {
    __shared__ int wsum[32];
    const int b    = blockIdx.x;
    const int tid  = threadIdx.x;
    const int lane = tid & 31;
    const int warp = tid >> 5;

    const int d = ds[b * T_ + tid];

    // warp-level inclusive scan
    int x = d;
    #pragma unroll
    for (int off = 1; off < 32; off <<= 1) {
        int y = __shfl_up_sync(0xffffffffu, x, off);
        if (lane >= off) x += y;
    }
    if (lane == 31) wsum[warp] = x;
    __syncthreads();

    if (warp == 0) {
        int w = wsum[lane];
        #pragma unroll
        for (int off = 1; off < 32; off <<= 1) {
            int y = __shfl_up_sync(0xffffffffu, w, off);
            if (lane >= off) w += y;
        }
        wsum[lane] = w;
    }
    __syncthreads();

    const int base  = (warp > 0) ? wsum[warp - 1] : 0;
    const int end   = base + x;          // inclusive cumsum for token tid
    const int start = end - d;
    const int total = wsum[31];

    int* __restrict__ gi = &g_idx[b * OUTLEN_];

    // scatter-expand: token tid covers output frames [start, end)
    for (int t = start; t < end; t++) gi[t] = tid;

    // pad tail
    for (int t = total + tid; t < OUTLEN_; t += T_) gi[t] = -1;
}

// ---------------------------------------------------------------------------
// Kernel 2: streaming gather with MLP=8. One CTA handles 32 output rows.
// Each thread owns 8 consecutive rows: 2x int4 idx loads, 8 independent
// gathers, 8 streaming stores.
// ---------------------------------------------------------------------------
__global__ void __launch_bounds__(G_THREADS) gather_kernel(
    const float4* __restrict__ xs, float4* __restrict__ out) {
    const int lr   = threadIdx.x / D4_;        // 0..3 slice of 8 rows
    const int c    = threadIdx.x - lr * D4_;   // 0..95 column
    const int row0 = blockIdx.x * ROWS_PER_CTA;
    const int myrow0 = row0 + lr * RPT;        // first of my 8 rows
    const int b    = row0 >> 12;               // same batch for whole CTA
    const float4* __restrict__ xb = xs + (size_t)b * T_ * D4_;

    // vectorized index fetch: 8 consecutive ints = 2x int4
    const int4* gi4 = (const int4*)&g_idx[myrow0];
    int4 ia = __ldg(&gi4[0]);
    int4 ib = __ldg(&gi4[1]);
    int idxs[RPT] = {ia.x, ia.y, ia.z, ia.w, ib.x, ib.y, ib.z, ib.w};

    // 8 independent gathers
    float4 v[RPT];
    #pragma unroll
    for (int k = 0; k < RPT; k++) {
        if (idxs[k] >= 0)
            v[k] = __ldg(&xb[(size_t)idxs[k] * D4_ + c]);
        else
            v[k] = make_float4(0.f, 0.f, 0.f, 0.f);
    }

    // streaming stores (write-once data, don't pollute L2)
    float4* o = out + (size_t)myrow0 * D4_ + c;
    #pragma unroll
    for (int k = 0; k < RPT; k++)
        __stcs(o + (size_t)k * D4_, v[k]);
}

extern "C" void kernel_launch(void* const* d_in, const int* in_sizes, int n_in,
                              void* d_out, int out_size) {
    const float* xs = (const float*)d_in[0];   // (16,1024,384) f32
    const int*   ds = (const int*)d_in[1];     // (16,1024) i32
    float* out = (float*)d_out;                // (16,4096,384) f32

    scan_idx_kernel<<<B_, T_>>>(ds);
    gather_kernel<<<(B_ * OUTLEN_) / ROWS_PER_CTA, G_THREADS>>>(
        (const float4*)xs, (float4*)out);
}